// round 3
// baseline (speedup 1.0000x reference)
#include <cuda_runtime.h>

#define BB 8
#define SS 32
#define PP 8
#define VV 8000
#define DD 128
#define CONCF 5.0f
#define EPSF 1e-8f

#define NT_ATTN 512
#define NQ (VV/4)        /* 2000 float4 per row */
#define TM 16            /* GEMM m-tile */
#define KSPLIT 16
#define VT (VV/KSPLIT)   /* 500 */
#define ASTRIDE 20       /* padded [v][m] stride to keep 16B alignment + reduce conflicts */

// ---------------- scratch (device globals, no allocations) ----------------
__device__ float g_cn[BB*DD];                 // normalized context [B,D]
__device__ float g_cos[BB*VV];                // |cosine sim| [B,V]
__device__ float g_Abar[(size_t)BB*SS*VV];    // summed attention rows [B*S, V] (8 MB)

// ---------------- helpers ----------------
__device__ __forceinline__ float warpReduceSum(float v){
    #pragma unroll
    for (int o = 16; o > 0; o >>= 1) v += __shfl_down_sync(0xffffffffu, v, o);
    return v;
}

// ---------------- kernel 1: context + normalize ----------------
__global__ void ctx_kernel(const int* __restrict__ concepts,
                           const int* __restrict__ clen,
                           const int* __restrict__ segl,
                           const float* __restrict__ embedw){
    int b = blockIdx.x;
    int d = threadIdx.x;            // 128 threads, one per D
    int seg = segl[b];
    float ctx = 0.f;
    for (int s = 0; s < seg; ++s){
        int len = clen[b*SS + s];
        float sum = 0.f;
        for (int p = 0; p < len; ++p){
            int c = concepts[(b*SS + s)*PP + p];
            sum += embedw[(size_t)c*DD + d];
        }
        float den = (len > 0) ? (float)len : 1.0f;
        ctx += sum / den;
    }
    ctx /= (float)seg;

    __shared__ float red[4];
    float sq = warpReduceSum(ctx*ctx);
    if ((d & 31) == 0) red[d >> 5] = sq;
    __syncthreads();
    float norm = sqrtf(red[0] + red[1] + red[2] + red[3]);
    g_cn[b*DD + d] = ctx / fmaxf(norm, EPSF);
}

// ---------------- kernel 2: abs cosine similarity vs kb table ----------------
__global__ void cos_kernel(const float* __restrict__ kb){
    int warp = threadIdx.x >> 5, lane = threadIdx.x & 31;
    int v = blockIdx.x*8 + warp;
    if (v >= VV) return;
    const float4* row4 = (const float4*)(kb + (size_t)v*DD);
    float4 kv = row4[lane];
    float nr = kv.x*kv.x + kv.y*kv.y + kv.z*kv.z + kv.w*kv.w;
    nr = warpReduceSum(nr);
    nr = __shfl_sync(0xffffffffu, nr, 0);
    float inv = 1.0f / fmaxf(sqrtf(nr), EPSF);
    #pragma unroll
    for (int b = 0; b < BB; ++b){
        const float4* cn4 = (const float4*)(g_cn + b*DD);
        float4 c = cn4[lane];
        float dt = kv.x*c.x + kv.y*c.y + kv.z*c.z + kv.w*c.w;
        dt = warpReduceSum(dt);
        if (lane == 0) g_cos[(size_t)b*VV + v] = fabsf(dt)*inv;
    }
}

// ---------------- kernel 3: per-(b,s) fused edge-normalize + w + softmax, summed over p ----------------
__global__ void __launch_bounds__(NT_ATTN)
attn_kernel(const int* __restrict__ concepts,
            const int* __restrict__ clen,
            const int* __restrict__ segl,
            const float* __restrict__ edge,
            const float* __restrict__ aff,
            const float* __restrict__ lam){
    __shared__ __align__(16) float wb[VV];   // row staging / exp values (32 KB)
    __shared__ float red[32];
    int bs = blockIdx.x;
    int b = bs >> 5, s = bs & 31;
    int tid = threadIdx.x;

    float4 racc[4];
    #pragma unroll
    for (int k = 0; k < 4; ++k) racc[k] = make_float4(0.f, 0.f, 0.f, 0.f);

    int seg = segl[b];
    int len = clen[bs];
    if (s < seg && len > 0){
        float invden = 1.0f / (float)len;
        const float4* cos4 = (const float4*)(g_cos + (size_t)b*VV);
        const float4* lam4 = (const float4*)lam;
        const float4* aff4 = (const float4*)aff;
        float4* wb4 = (float4*)wb;

        for (int p = 0; p < len; ++p){
            int c = concepts[bs*PP + p];
            const float4* row4 = (const float4*)(edge + (size_t)c*VV);

            // pass 1: load row to smem, row min/max (for range normalization)
            float mx = -1e30f, mn = 1e30f;
            #pragma unroll
            for (int k = 0; k < 4; ++k){
                int i = tid + k*NT_ATTN;
                if (i < NQ){
                    float4 e = row4[i];
                    wb4[i] = e;
                    mx = fmaxf(mx, fmaxf(fmaxf(e.x, e.y), fmaxf(e.z, e.w)));
                    mn = fminf(mn, fminf(fminf(e.x, e.y), fminf(e.z, e.w)));
                }
            }
            #pragma unroll
            for (int o = 16; o > 0; o >>= 1){
                mx = fmaxf(mx, __shfl_down_sync(0xffffffffu, mx, o));
                mn = fminf(mn, __shfl_down_sync(0xffffffffu, mn, o));
            }
            __syncthreads();
            if ((tid & 31) == 0){ red[tid >> 5] = mx; red[16 + (tid >> 5)] = mn; }
            __syncthreads();
            float rmx = -1e30f, rmn = 1e30f;
            #pragma unroll
            for (int i = 0; i < 16; ++i){
                rmx = fmaxf(rmx, red[i]);
                rmn = fminf(rmn, red[16 + i]);
            }
            float rng  = rmx - rmn;
            float invr = 1.0f / (rng + ((rng == 0.0f) ? 1.0f : 0.0f));

            // pass 2: w = lam*em*cos + (1-lam)*(em>0)*aff ; exp(w*CONC) ; partial sum
            // (w*CONC in [0, ~5.2] for this data, so no max-subtraction needed: exp <= ~200)
            float ss = 0.f;
            #pragma unroll
            for (int k = 0; k < 4; ++k){
                int i = tid + k*NT_ATTN;
                if (i < NQ){
                    float4 e  = wb4[i];
                    float4 l  = lam4[i];
                    float4 cf = cos4[i];
                    float4 af = aff4[i];
                    float4 ex;
                    ex.x = __expf(CONCF*(l.x*(e.x*invr)*cf.x + (1.f - l.x)*((e.x > 0.f) ? af.x : 0.f)));
                    ex.y = __expf(CONCF*(l.y*(e.y*invr)*cf.y + (1.f - l.y)*((e.y > 0.f) ? af.y : 0.f)));
                    ex.z = __expf(CONCF*(l.z*(e.z*invr)*cf.z + (1.f - l.z)*((e.z > 0.f) ? af.z : 0.f)));
                    ex.w = __expf(CONCF*(l.w*(e.w*invr)*cf.w + (1.f - l.w)*((e.w > 0.f) ? af.w : 0.f)));
                    wb4[i] = ex;
                    ss += (ex.x + ex.y) + (ex.z + ex.w);
                }
            }
            ss = warpReduceSum(ss);
            __syncthreads();
            if ((tid & 31) == 0) red[tid >> 5] = ss;
            __syncthreads();
            float tot = 0.f;
            #pragma unroll
            for (int i = 0; i < 16; ++i) tot += red[i];
            float scale = invden / tot;

            // pass 3: accumulate softmax/denom into per-thread registers
            #pragma unroll
            for (int k = 0; k < 4; ++k){
                int i = tid + k*NT_ATTN;
                if (i < NQ){
                    float4 ex = wb4[i];
                    racc[k].x += ex.x*scale;
                    racc[k].y += ex.y*scale;
                    racc[k].z += ex.z*scale;
                    racc[k].w += ex.w*scale;
                }
            }
            // no extra barrier needed: wb4/racc strictly thread-private stripes;
            // red is protected by the leading __syncthreads of the next reduction
        }
    }
    // write Abar row (zeros for masked rows)
    float4* ob = (float4*)(g_Abar + (size_t)bs*VV);
    #pragma unroll
    for (int k = 0; k < 4; ++k){
        int i = tid + k*NT_ATTN;
        if (i < NQ) ob[i] = racc[k];
    }
}

// ---------------- kernel 4: zero output ----------------
__global__ void zero_kernel(float* __restrict__ out){
    int i = blockIdx.x*blockDim.x + threadIdx.x;
    if (i < BB*SS*DD) out[i] = 0.f;
}

// ---------------- kernel 5: out[256,128] = Abar[256,8000] @ kb[8000,128] ----------------
__global__ void __launch_bounds__(256)
gemm_kernel(const float* __restrict__ kb,
            const int* __restrict__ segl,
            float* __restrict__ out){
    __shared__ __align__(16) float As[VT*ASTRIDE];   // [v][m], 40 KB
    int mt = blockIdx.x, ks = blockIdx.y;
    int m0 = mt*TM;
    int b  = m0 >> 5, s0 = m0 & 31;
    if (s0 >= segl[b]) return;                       // whole tile masked -> out stays zero
    int tid = threadIdx.x;
    int v0  = ks*VT;

    for (int idx = tid; idx < TM*VT; idx += 256){
        int m = idx / VT;
        int v = idx - m*VT;
        As[v*ASTRIDE + m] = g_Abar[(size_t)(m0 + m)*VV + v0 + v];
    }
    __syncthreads();

    int d    = tid & (DD - 1);
    int half = tid >> 7;
    unsigned long long acc2[TM/2];
    #pragma unroll
    for (int m = 0; m < TM/2; ++m) acc2[m] = 0ULL;

    const float* kbp = kb + (size_t)v0*DD + d;
    int vbeg = half*(VT/2), vend = vbeg + VT/2;
    for (int v = vbeg; v < vend; ++v){
        float kv = kbp[(size_t)v*DD];
        unsigned long long kv2;
        asm("mov.b64 %0, {%1,%2};" : "=l"(kv2) : "f"(kv), "f"(kv));
        const double2* a2 = (const double2*)(As + v*ASTRIDE);
        double2 q0 = a2[0];
        double2 q1 = a2[1];
        double2 q2 = a2[2];
        double2 q3 = a2[3];
        asm("fma.rn.f32x2 %0, %1, %2, %0;" : "+l"(acc2[0]) : "l"(__double_as_longlong(q0.x)), "l"(kv2));
        asm("fma.rn.f32x2 %0, %1, %2, %0;" : "+l"(acc2[1]) : "l"(__double_as_longlong(q0.y)), "l"(kv2));
        asm("fma.rn.f32x2 %0, %1, %2, %0;" : "+l"(acc2[2]) : "l"(__double_as_longlong(q1.x)), "l"(kv2));
        asm("fma.rn.f32x2 %0, %1, %2, %0;" : "+l"(acc2[3]) : "l"(__double_as_longlong(q1.y)), "l"(kv2));
        asm("fma.rn.f32x2 %0, %1, %2, %0;" : "+l"(acc2[4]) : "l"(__double_as_longlong(q2.x)), "l"(kv2));
        asm("fma.rn.f32x2 %0, %1, %2, %0;" : "+l"(acc2[5]) : "l"(__double_as_longlong(q2.y)), "l"(kv2));
        asm("fma.rn.f32x2 %0, %1, %2, %0;" : "+l"(acc2[6]) : "l"(__double_as_longlong(q3.x)), "l"(kv2));
        asm("fma.rn.f32x2 %0, %1, %2, %0;" : "+l"(acc2[7]) : "l"(__double_as_longlong(q3.y)), "l"(kv2));
    }

    float accf[TM];
    #pragma unroll
    for (int m = 0; m < TM/2; ++m){
        float lo, hi;
        asm("mov.b64 {%0,%1}, %2;" : "=f"(lo), "=f"(hi) : "l"(acc2[m]));
        accf[2*m]     = lo;
        accf[2*m + 1] = hi;
    }

    __syncthreads();               // As no longer needed; reuse for half-combine
    float* redm = As;              // needs 16*128 floats = 8 KB
    if (half == 1){
        #pragma unroll
        for (int m = 0; m < TM; ++m) redm[m*DD + d] = accf[m];
    }
    __syncthreads();
    if (half == 0){
        #pragma unroll
        for (int m = 0; m < TM; ++m){
            atomicAdd(&out[(size_t)(m0 + m)*DD + d], accf[m] + redm[m*DD + d]);
        }
    }
}

// ---------------- launch ----------------
extern "C" void kernel_launch(void* const* d_in, const int* in_sizes, int n_in,
                              void* d_out, int out_size){
    (void)in_sizes; (void)n_in; (void)out_size;
    const int*   concepts = (const int*)  d_in[0];
    const int*   clen     = (const int*)  d_in[1];
    const int*   segl     = (const int*)  d_in[2];
    const float* embedw   = (const float*)d_in[3];
    const float* kb       = (const float*)d_in[4];
    const float* edge     = (const float*)d_in[5];
    const float* aff      = (const float*)d_in[6];
    const float* lam      = (const float*)d_in[7];
    float* out = (float*)d_out;

    ctx_kernel <<<BB, DD>>>(concepts, clen, segl, embedw);
    cos_kernel <<<VV/8, 256>>>(kb);
    attn_kernel<<<BB*SS, NT_ATTN>>>(concepts, clen, segl, edge, aff, lam);
    zero_kernel<<<(BB*SS*DD + 255)/256, 256>>>(out);
    gemm_kernel<<<dim3(16, KSPLIT), 256>>>(kb, segl, out);
}

// round 4
// speedup vs baseline: 1.3959x; 1.3959x over previous
#include <cuda_runtime.h>

#define BB 8
#define SS 32
#define PP 8
#define VV 8000
#define DD 128
#define CONCF 5.0f
#define EPSF 1e-8f

#define NT_ATTN 512
#define NQ (VV/4)        /* 2000 float4 per row */
#define TM 16            /* GEMM m-tile */
#define KSPLIT 16
#define VT (VV/KSPLIT)   /* 500 */
#define ASTRIDE 20

// ---------------- scratch (device globals, no allocations) ----------------
__device__ float g_cn[BB*DD];                 // normalized context [B,D]
__device__ float g_cos[BB*VV];                // |cosine sim| [B,V]
__device__ float g_Abar[(size_t)BB*SS*VV];    // summed attention rows [B*S, V] (8 MB)

__device__ __forceinline__ float warpReduceSum(float v){
    #pragma unroll
    for (int o = 16; o > 0; o >>= 1) v += __shfl_down_sync(0xffffffffu, v, o);
    return v;
}

// ---------------- kernel 1: context + normalize (parallel over s) ----------------
__global__ void __launch_bounds__(1024)
ctx_kernel(const int* __restrict__ concepts,
           const int* __restrict__ clen,
           const int* __restrict__ segl,
           const float* __restrict__ embedw){
    __shared__ float sm[8*DD];
    __shared__ float redn[32];
    int b = blockIdx.x;
    int g = threadIdx.x >> 7;        // s-group 0..7
    int d = threadIdx.x & 127;
    int seg = segl[b];

    float part = 0.f;
    for (int s = g; s < seg; s += 8){
        int bs = b*SS + s;
        int len = clen[bs];
        if (len > 0){
            const int4* ci = (const int4*)(concepts + bs*PP);
            int4 c0 = ci[0], c1 = ci[1];
            int idx0 = c0.x, idx1 = c0.y, idx2 = c0.z, idx3 = c0.w;
            int idx4 = c1.x, idx5 = c1.y, idx6 = c1.z, idx7 = c1.w;
            float sum = 0.f;
            // predicated, independent gathers (MLP up to 8)
            if (0 < len) sum += __ldg(&embedw[(size_t)idx0*DD + d]);
            if (1 < len) sum += __ldg(&embedw[(size_t)idx1*DD + d]);
            if (2 < len) sum += __ldg(&embedw[(size_t)idx2*DD + d]);
            if (3 < len) sum += __ldg(&embedw[(size_t)idx3*DD + d]);
            if (4 < len) sum += __ldg(&embedw[(size_t)idx4*DD + d]);
            if (5 < len) sum += __ldg(&embedw[(size_t)idx5*DD + d]);
            if (6 < len) sum += __ldg(&embedw[(size_t)idx6*DD + d]);
            if (7 < len) sum += __ldg(&embedw[(size_t)idx7*DD + d]);
            part += sum / (float)len;
        }
    }
    sm[g*DD + d] = part;
    __syncthreads();

    float ctx = 0.f;
    #pragma unroll
    for (int k = 0; k < 8; ++k) ctx += sm[k*DD + d];
    ctx /= (float)seg;

    int warp = threadIdx.x >> 5, lane = threadIdx.x & 31;
    float sq = warpReduceSum(ctx*ctx);
    if (lane == 0) redn[warp] = sq;
    __syncthreads();
    // warps 0..3 cover d=0..127 exactly once
    float n2 = redn[0] + redn[1] + redn[2] + redn[3];
    if (g == 0) g_cn[b*DD + d] = ctx / fmaxf(sqrtf(n2), EPSF);
}

// ---------------- kernel 2: abs cosine sim + fused output zeroing ----------------
__global__ void cos_kernel(const float* __restrict__ kb, float* __restrict__ out){
    // fold the old zero_kernel into the first 128 blocks
    if (blockIdx.x < (BB*SS*DD)/256)
        out[blockIdx.x*256 + threadIdx.x] = 0.f;

    int warp = threadIdx.x >> 5, lane = threadIdx.x & 31;
    int v = blockIdx.x*8 + warp;
    if (v >= VV) return;
    const float4* row4 = (const float4*)(kb + (size_t)v*DD);
    float4 kv = row4[lane];
    float nr = kv.x*kv.x + kv.y*kv.y + kv.z*kv.z + kv.w*kv.w;
    nr = warpReduceSum(nr);
    nr = __shfl_sync(0xffffffffu, nr, 0);
    float inv = 1.0f / fmaxf(sqrtf(nr), EPSF);
    #pragma unroll
    for (int b = 0; b < BB; ++b){
        const float4* cn4 = (const float4*)(g_cn + b*DD);
        float4 c = cn4[lane];
        float dt = kv.x*c.x + kv.y*c.y + kv.z*c.z + kv.w*c.w;
        dt = warpReduceSum(dt);
        if (lane == 0) g_cos[(size_t)b*VV + v] = fabsf(dt)*inv;
    }
}

// ---------------- kernel 3: register-resident fused attention ----------------
__global__ void __launch_bounds__(NT_ATTN, 1)
attn_kernel(const int* __restrict__ concepts,
            const int* __restrict__ clen,
            const int* __restrict__ segl,
            const float* __restrict__ edge,
            const float* __restrict__ aff,
            const float* __restrict__ lam){
    __shared__ float red[32];
    int bs = blockIdx.x;
    int b = bs >> 5, s = bs & 31;
    int tid = threadIdx.x;
    int warp = tid >> 5, lane = tid & 31;

    float4 racc[4];
    #pragma unroll
    for (int k = 0; k < 4; ++k) racc[k] = make_float4(0.f, 0.f, 0.f, 0.f);

    int seg = segl[b];
    int len = (s < seg) ? clen[bs] : 0;

    if (len > 0){
        float invden = 1.0f / (float)len;
        const float4* cos4 = (const float4*)(g_cos + (size_t)b*VV);
        const float4* lam4 = (const float4*)lam;
        const float4* aff4 = (const float4*)aff;
        const int*    cp   = concepts + bs*PP;

        // hoisted per-element coefficients (loaded ONCE, reused for every p)
        // A = CONC*lam*cos, Bv = CONC*(1-lam)*aff
        float4 A[4], Bv[4];
        #pragma unroll
        for (int k = 0; k < 4; ++k){
            int i = tid + k*NT_ATTN;
            if (i < NQ){
                float4 l  = lam4[i];
                float4 cf = cos4[i];
                float4 af = aff4[i];
                A[k].x = CONCF*l.x*cf.x; A[k].y = CONCF*l.y*cf.y;
                A[k].z = CONCF*l.z*cf.z; A[k].w = CONCF*l.w*cf.w;
                Bv[k].x = CONCF*(1.f-l.x)*af.x; Bv[k].y = CONCF*(1.f-l.y)*af.y;
                Bv[k].z = CONCF*(1.f-l.z)*af.z; Bv[k].w = CONCF*(1.f-l.w)*af.w;
            }
        }

        float4 E[4], F[4];
        // load p=0 edge row (streaming hint: rows are ~unique, keep L2 for kb/cos/lam)
        {
            int c = __ldg(&cp[0]);
            const float4* r = (const float4*)(edge + (size_t)c*VV);
            #pragma unroll
            for (int k = 0; k < 4; ++k){
                int i = tid + k*NT_ATTN;
                if (i < NQ) E[k] = __ldcs(&r[i]);
            }
        }

        for (int p = 0; p < len; ++p){
            // prefetch next row while we crunch the current one
            if (p + 1 < len){
                int c = __ldg(&cp[p+1]);
                const float4* r = (const float4*)(edge + (size_t)c*VV);
                #pragma unroll
                for (int k = 0; k < 4; ++k){
                    int i = tid + k*NT_ATTN;
                    if (i < NQ) F[k] = __ldcs(&r[i]);
                }
            }

            // block min/max for range normalization
            float mx = -1e30f, mn = 1e30f;
            #pragma unroll
            for (int k = 0; k < 4; ++k){
                int i = tid + k*NT_ATTN;
                if (i < NQ){
                    mx = fmaxf(mx, fmaxf(fmaxf(E[k].x, E[k].y), fmaxf(E[k].z, E[k].w)));
                    mn = fminf(mn, fminf(fminf(E[k].x, E[k].y), fminf(E[k].z, E[k].w)));
                }
            }
            #pragma unroll
            for (int o = 16; o > 0; o >>= 1){
                mx = fmaxf(mx, __shfl_down_sync(0xffffffffu, mx, o));
                mn = fminf(mn, __shfl_down_sync(0xffffffffu, mn, o));
            }
            __syncthreads();                 // protect red from previous iteration's readers
            if (lane == 0){ red[warp] = mx; red[16 + warp] = mn; }
            __syncthreads();
            float rmx = -1e30f, rmn = 1e30f;
            #pragma unroll
            for (int i = 0; i < 16; ++i){
                rmx = fmaxf(rmx, red[i]);
                rmn = fminf(rmn, red[16 + i]);
            }
            float rng  = rmx - rmn;
            float invr = 1.0f / (rng + ((rng == 0.0f) ? 1.0f : 0.0f));

            // exp(w*CONC) in registers; w*CONC in [0,~5.2] so no max-subtract needed
            float ss = 0.f;
            #pragma unroll
            for (int k = 0; k < 4; ++k){
                int i = tid + k*NT_ATTN;
                if (i < NQ){
                    float4 ex;
                    ex.x = __expf((E[k].x*invr)*A[k].x + ((E[k].x > 0.f) ? Bv[k].x : 0.f));
                    ex.y = __expf((E[k].y*invr)*A[k].y + ((E[k].y > 0.f) ? Bv[k].y : 0.f));
                    ex.z = __expf((E[k].z*invr)*A[k].z + ((E[k].z > 0.f) ? Bv[k].z : 0.f));
                    ex.w = __expf((E[k].w*invr)*A[k].w + ((E[k].w > 0.f) ? Bv[k].w : 0.f));
                    E[k] = ex;
                    ss += (ex.x + ex.y) + (ex.z + ex.w);
                }
            }
            ss = warpReduceSum(ss);
            __syncthreads();
            if (lane == 0) red[warp] = ss;
            __syncthreads();
            float tot = 0.f;
            #pragma unroll
            for (int i = 0; i < 16; ++i) tot += red[i];
            float scale = invden / tot;

            #pragma unroll
            for (int k = 0; k < 4; ++k){
                int i = tid + k*NT_ATTN;
                if (i < NQ){
                    racc[k].x += E[k].x*scale;
                    racc[k].y += E[k].y*scale;
                    racc[k].z += E[k].z*scale;
                    racc[k].w += E[k].w*scale;
                }
            }
            #pragma unroll
            for (int k = 0; k < 4; ++k) E[k] = F[k];
        }
    }

    float4* ob = (float4*)(g_Abar + (size_t)bs*VV);
    #pragma unroll
    for (int k = 0; k < 4; ++k){
        int i = tid + k*NT_ATTN;
        if (i < NQ) ob[i] = racc[k];
    }
}

// ---------------- kernel 4: out[256,128] = Abar[256,8000] @ kb[8000,128] ----------------
__global__ void __launch_bounds__(256)
gemm_kernel(const float* __restrict__ kb,
            const int* __restrict__ segl,
            float* __restrict__ out){
    __shared__ __align__(16) float As[VT*ASTRIDE];   // [v][m], 40 KB
    int mt = blockIdx.x, ks = blockIdx.y;
    int m0 = mt*TM;
    int b  = m0 >> 5, s0 = m0 & 31;
    if (s0 >= segl[b]) return;                       // whole tile masked -> out stays zero
    int tid = threadIdx.x;
    int v0  = ks*VT;

    for (int idx = tid; idx < TM*VT; idx += 256){
        int m = idx / VT;
        int v = idx - m*VT;
        As[v*ASTRIDE + m] = g_Abar[(size_t)(m0 + m)*VV + v0 + v];
    }
    __syncthreads();

    int d    = tid & (DD - 1);
    int half = tid >> 7;
    unsigned long long acc2[TM/2];
    #pragma unroll
    for (int m = 0; m < TM/2; ++m) acc2[m] = 0ULL;

    const float* kbp = kb + (size_t)v0*DD + d;
    int vbeg = half*(VT/2), vend = vbeg + VT/2;
    #pragma unroll 2
    for (int v = vbeg; v < vend; ++v){
        float kv = __ldg(&kbp[(size_t)v*DD]);
        unsigned long long kv2;
        asm("mov.b64 %0, {%1,%2};" : "=l"(kv2) : "f"(kv), "f"(kv));
        const double2* a2 = (const double2*)(As + v*ASTRIDE);
        double2 q0 = a2[0];
        double2 q1 = a2[1];
        double2 q2 = a2[2];
        double2 q3 = a2[3];
        asm("fma.rn.f32x2 %0, %1, %2, %0;" : "+l"(acc2[0]) : "l"(__double_as_longlong(q0.x)), "l"(kv2));
        asm("fma.rn.f32x2 %0, %1, %2, %0;" : "+l"(acc2[1]) : "l"(__double_as_longlong(q0.y)), "l"(kv2));
        asm("fma.rn.f32x2 %0, %1, %2, %0;" : "+l"(acc2[2]) : "l"(__double_as_longlong(q1.x)), "l"(kv2));
        asm("fma.rn.f32x2 %0, %1, %2, %0;" : "+l"(acc2[3]) : "l"(__double_as_longlong(q1.y)), "l"(kv2));
        asm("fma.rn.f32x2 %0, %1, %2, %0;" : "+l"(acc2[4]) : "l"(__double_as_longlong(q2.x)), "l"(kv2));
        asm("fma.rn.f32x2 %0, %1, %2, %0;" : "+l"(acc2[5]) : "l"(__double_as_longlong(q2.y)), "l"(kv2));
        asm("fma.rn.f32x2 %0, %1, %2, %0;" : "+l"(acc2[6]) : "l"(__double_as_longlong(q3.x)), "l"(kv2));
        asm("fma.rn.f32x2 %0, %1, %2, %0;" : "+l"(acc2[7]) : "l"(__double_as_longlong(q3.y)), "l"(kv2));
    }

    float accf[TM];
    #pragma unroll
    for (int m = 0; m < TM/2; ++m){
        float lo, hi;
        asm("mov.b64 {%0,%1}, %2;" : "=f"(lo), "=f"(hi) : "l"(acc2[m]));
        accf[2*m]     = lo;
        accf[2*m + 1] = hi;
    }

    __syncthreads();               // As no longer needed; reuse for half-combine
    float* redm = As;
    if (half == 1){
        #pragma unroll
        for (int m = 0; m < TM; ++m) redm[m*DD + d] = accf[m];
    }
    __syncthreads();
    if (half == 0){
        #pragma unroll
        for (int m = 0; m < TM; ++m){
            atomicAdd(&out[(size_t)(m0 + m)*DD + d], accf[m] + redm[m*DD + d]);
        }
    }
}

// ---------------- launch ----------------
extern "C" void kernel_launch(void* const* d_in, const int* in_sizes, int n_in,
                              void* d_out, int out_size){
    (void)in_sizes; (void)n_in; (void)out_size;
    const int*   concepts = (const int*)  d_in[0];
    const int*   clen     = (const int*)  d_in[1];
    const int*   segl     = (const int*)  d_in[2];
    const float* embedw   = (const float*)d_in[3];
    const float* kb       = (const float*)d_in[4];
    const float* edge     = (const float*)d_in[5];
    const float* aff      = (const float*)d_in[6];
    const float* lam      = (const float*)d_in[7];
    float* out = (float*)d_out;

    ctx_kernel <<<BB, 1024>>>(concepts, clen, segl, embedw);
    cos_kernel <<<VV/8, 256>>>(kb, out);
    attn_kernel<<<BB*SS, NT_ATTN>>>(concepts, clen, segl, edge, aff, lam);
    gemm_kernel<<<dim3(16, KSPLIT), 256>>>(kb, segl, out);
}

// round 5
// speedup vs baseline: 1.4781x; 1.0589x over previous
#include <cuda_runtime.h>

#define BB 8
#define SS 32
#define PP 8
#define VV 8000
#define DD 128
#define CONCF 5.0f
#define EPSF 1e-8f

#define NT_ATTN 512
#define NQ (VV/4)        /* 2000 float4 per row */
#define TM 16            /* GEMM m-tile */
#define KSPLIT 32
#define VT (VV/KSPLIT)   /* 250 */
#define VH (VT/2)        /* 125 per half */
#define KB 5             /* kv prefetch batch */
#define ASTRIDE 20       /* 16B-aligned padded [v][m] stride */

// ---------------- scratch (device globals, no allocations) ----------------
__device__ float g_cn[BB*DD];                 // normalized context [B,D]
__device__ float g_cos[BB*VV];                // |cosine sim| [B,V]
__device__ float g_Abar[(size_t)BB*SS*VV];    // summed attention rows [B*S, V] (8 MB)

__device__ __forceinline__ float warpReduceSum(float v){
    #pragma unroll
    for (int o = 16; o > 0; o >>= 1) v += __shfl_down_sync(0xffffffffu, v, o);
    return v;
}

// ---------------- kernel 1: context + normalize (parallel over s) ----------------
__global__ void __launch_bounds__(1024)
ctx_kernel(const int* __restrict__ concepts,
           const int* __restrict__ clen,
           const int* __restrict__ segl,
           const float* __restrict__ embedw){
    __shared__ float sm[8*DD];
    __shared__ float redn[32];
    int b = blockIdx.x;
    int g = threadIdx.x >> 7;        // s-group 0..7
    int d = threadIdx.x & 127;
    int seg = segl[b];

    float part = 0.f;
    for (int s = g; s < seg; s += 8){
        int bs = b*SS + s;
        int len = clen[bs];
        if (len > 0){
            const int4* ci = (const int4*)(concepts + bs*PP);
            int4 c0 = ci[0], c1 = ci[1];
            float sum = 0.f;
            if (0 < len) sum += __ldg(&embedw[(size_t)c0.x*DD + d]);
            if (1 < len) sum += __ldg(&embedw[(size_t)c0.y*DD + d]);
            if (2 < len) sum += __ldg(&embedw[(size_t)c0.z*DD + d]);
            if (3 < len) sum += __ldg(&embedw[(size_t)c0.w*DD + d]);
            if (4 < len) sum += __ldg(&embedw[(size_t)c1.x*DD + d]);
            if (5 < len) sum += __ldg(&embedw[(size_t)c1.y*DD + d]);
            if (6 < len) sum += __ldg(&embedw[(size_t)c1.z*DD + d]);
            if (7 < len) sum += __ldg(&embedw[(size_t)c1.w*DD + d]);
            part += sum / (float)len;
        }
    }
    sm[g*DD + d] = part;
    __syncthreads();

    float ctx = 0.f;
    #pragma unroll
    for (int k = 0; k < 8; ++k) ctx += sm[k*DD + d];
    ctx /= (float)seg;

    int warp = threadIdx.x >> 5, lane = threadIdx.x & 31;
    float sq = warpReduceSum(ctx*ctx);
    if (lane == 0) redn[warp] = sq;
    __syncthreads();
    float n2 = redn[0] + redn[1] + redn[2] + redn[3];
    if (g == 0) g_cn[b*DD + d] = ctx / fmaxf(sqrtf(n2), EPSF);
}

// ---------------- kernel 2: abs cosine sim + fused output zeroing ----------------
__global__ void cos_kernel(const float* __restrict__ kb, float* __restrict__ out){
    if (blockIdx.x < (BB*SS*DD)/256)
        out[blockIdx.x*256 + threadIdx.x] = 0.f;

    int warp = threadIdx.x >> 5, lane = threadIdx.x & 31;
    int v = blockIdx.x*8 + warp;
    if (v >= VV) return;
    const float4* row4 = (const float4*)(kb + (size_t)v*DD);
    float4 kv = row4[lane];
    float nr = kv.x*kv.x + kv.y*kv.y + kv.z*kv.z + kv.w*kv.w;
    nr = warpReduceSum(nr);
    nr = __shfl_sync(0xffffffffu, nr, 0);
    float inv = 1.0f / fmaxf(sqrtf(nr), EPSF);
    #pragma unroll
    for (int b = 0; b < BB; ++b){
        const float4* cn4 = (const float4*)(g_cn + b*DD);
        float4 c = cn4[lane];
        float dt = kv.x*c.x + kv.y*c.y + kv.z*c.z + kv.w*c.w;
        dt = warpReduceSum(dt);
        if (lane == 0) g_cos[(size_t)b*VV + v] = fabsf(dt)*inv;
    }
}

// ---------------- kernel 3: register-resident fused attention ----------------
__global__ void __launch_bounds__(NT_ATTN, 1)
attn_kernel(const int* __restrict__ concepts,
            const int* __restrict__ clen,
            const int* __restrict__ segl,
            const float* __restrict__ edge,
            const float* __restrict__ aff,
            const float* __restrict__ lam){
    __shared__ float red[32];
    int bs = blockIdx.x;
    int b = bs >> 5, s = bs & 31;
    int tid = threadIdx.x;
    int warp = tid >> 5, lane = tid & 31;

    float4 racc[4];
    #pragma unroll
    for (int k = 0; k < 4; ++k) racc[k] = make_float4(0.f, 0.f, 0.f, 0.f);

    int seg = segl[b];
    int len = (s < seg) ? clen[bs] : 0;

    if (len > 0){
        float invden = 1.0f / (float)len;
        const float4* cos4 = (const float4*)(g_cos + (size_t)b*VV);
        const float4* lam4 = (const float4*)lam;
        const float4* aff4 = (const float4*)aff;
        const int*    cp   = concepts + bs*PP;

        // hoisted coefficients: A = CONC*lam*cos, Bv = CONC*(1-lam)*aff
        float4 A[4], Bv[4];
        #pragma unroll
        for (int k = 0; k < 4; ++k){
            int i = tid + k*NT_ATTN;
            if (i < NQ){
                float4 l  = lam4[i];
                float4 cf = cos4[i];
                float4 af = aff4[i];
                A[k].x = CONCF*l.x*cf.x; A[k].y = CONCF*l.y*cf.y;
                A[k].z = CONCF*l.z*cf.z; A[k].w = CONCF*l.w*cf.w;
                Bv[k].x = CONCF*(1.f-l.x)*af.x; Bv[k].y = CONCF*(1.f-l.y)*af.y;
                Bv[k].z = CONCF*(1.f-l.z)*af.z; Bv[k].w = CONCF*(1.f-l.w)*af.w;
            }
        }

        float4 E[4], F[4];
        {
            int c = __ldg(&cp[0]);
            const float4* r = (const float4*)(edge + (size_t)c*VV);
            #pragma unroll
            for (int k = 0; k < 4; ++k){
                int i = tid + k*NT_ATTN;
                if (i < NQ) E[k] = __ldcs(&r[i]);
            }
        }

        for (int p = 0; p < len; ++p){
            if (p + 1 < len){
                int c = __ldg(&cp[p+1]);
                const float4* r = (const float4*)(edge + (size_t)c*VV);
                #pragma unroll
                for (int k = 0; k < 4; ++k){
                    int i = tid + k*NT_ATTN;
                    if (i < NQ) F[k] = __ldcs(&r[i]);
                }
            }

            float mx = -1e30f, mn = 1e30f;
            #pragma unroll
            for (int k = 0; k < 4; ++k){
                int i = tid + k*NT_ATTN;
                if (i < NQ){
                    mx = fmaxf(mx, fmaxf(fmaxf(E[k].x, E[k].y), fmaxf(E[k].z, E[k].w)));
                    mn = fminf(mn, fminf(fminf(E[k].x, E[k].y), fminf(E[k].z, E[k].w)));
                }
            }
            #pragma unroll
            for (int o = 16; o > 0; o >>= 1){
                mx = fmaxf(mx, __shfl_down_sync(0xffffffffu, mx, o));
                mn = fminf(mn, __shfl_down_sync(0xffffffffu, mn, o));
            }
            __syncthreads();
            if (lane == 0){ red[warp] = mx; red[16 + warp] = mn; }
            __syncthreads();
            float rmx = -1e30f, rmn = 1e30f;
            #pragma unroll
            for (int i = 0; i < 16; ++i){
                rmx = fmaxf(rmx, red[i]);
                rmn = fminf(rmn, red[16 + i]);
            }
            float rng  = rmx - rmn;
            float invr = 1.0f / (rng + ((rng == 0.0f) ? 1.0f : 0.0f));

            float ss = 0.f;
            #pragma unroll
            for (int k = 0; k < 4; ++k){
                int i = tid + k*NT_ATTN;
                if (i < NQ){
                    float4 ex;
                    ex.x = __expf((E[k].x*invr)*A[k].x + ((E[k].x > 0.f) ? Bv[k].x : 0.f));
                    ex.y = __expf((E[k].y*invr)*A[k].y + ((E[k].y > 0.f) ? Bv[k].y : 0.f));
                    ex.z = __expf((E[k].z*invr)*A[k].z + ((E[k].z > 0.f) ? Bv[k].z : 0.f));
                    ex.w = __expf((E[k].w*invr)*A[k].w + ((E[k].w > 0.f) ? Bv[k].w : 0.f));
                    E[k] = ex;
                    ss += (ex.x + ex.y) + (ex.z + ex.w);
                }
            }
            ss = warpReduceSum(ss);
            __syncthreads();
            if (lane == 0) red[warp] = ss;
            __syncthreads();
            float tot = 0.f;
            #pragma unroll
            for (int i = 0; i < 16; ++i) tot += red[i];
            float scale = invden / tot;

            #pragma unroll
            for (int k = 0; k < 4; ++k){
                int i = tid + k*NT_ATTN;
                if (i < NQ){
                    racc[k].x += E[k].x*scale;
                    racc[k].y += E[k].y*scale;
                    racc[k].z += E[k].z*scale;
                    racc[k].w += E[k].w*scale;
                }
            }
            #pragma unroll
            for (int k = 0; k < 4; ++k) E[k] = F[k];
        }
    }

    float4* ob = (float4*)(g_Abar + (size_t)bs*VV);
    #pragma unroll
    for (int k = 0; k < 4; ++k){
        int i = tid + k*NT_ATTN;
        if (i < NQ) ob[i] = racc[k];
    }
}

// ---------------- kernel 4: out[256,128] = Abar[256,8000] @ kb[8000,128] ----------------
__global__ void __launch_bounds__(256)
gemm_kernel(const float* __restrict__ kb,
            const int* __restrict__ segl,
            float* __restrict__ out){
    __shared__ __align__(16) float As[VT*ASTRIDE];   // [v][m], 20 KB
    int mt = blockIdx.x, ks = blockIdx.y;
    int m0 = mt*TM;
    int b  = m0 >> 5, s0 = m0 & 31;
    if (s0 >= segl[b]) return;                       // whole tile masked -> out stays zero
    int tid = threadIdx.x;
    int v0  = ks*VT;

    for (int idx = tid; idx < TM*VT; idx += 256){
        int m = idx / VT;
        int v = idx - m*VT;
        As[v*ASTRIDE + m] = __ldcs(&g_Abar[(size_t)(m0 + m)*VV + v0 + v]);
    }
    __syncthreads();

    int d    = tid & (DD - 1);
    int half = tid >> 7;
    unsigned long long acc2[TM/2];
    #pragma unroll
    for (int m = 0; m < TM/2; ++m) acc2[m] = 0ULL;

    int vbeg = half*VH;
    const float* kbp = kb + (size_t)(v0 + vbeg)*DD + d;

    // double-buffered batched kv prefetch: MLP >= 5, hides L2 latency
    float kva[KB], kvb[KB];
    #pragma unroll
    for (int j = 0; j < KB; ++j) kva[j] = __ldg(&kbp[(size_t)j*DD]);

    for (int t = 0; t < VH/KB; ++t){
        if (t + 1 < VH/KB){
            const float* nxt = kbp + (size_t)(t+1)*KB*DD;
            #pragma unroll
            for (int j = 0; j < KB; ++j) kvb[j] = __ldg(&nxt[(size_t)j*DD]);
        }
        const float* asb = As + (vbeg + t*KB)*ASTRIDE;
        #pragma unroll
        for (int j = 0; j < KB; ++j){
            unsigned long long kv2;
            asm("mov.b64 %0, {%1,%2};" : "=l"(kv2) : "f"(kva[j]), "f"(kva[j]));
            const double2* a2 = (const double2*)(asb + j*ASTRIDE);
            double2 q0 = a2[0];
            double2 q1 = a2[1];
            double2 q2 = a2[2];
            double2 q3 = a2[3];
            asm("fma.rn.f32x2 %0, %1, %2, %0;" : "+l"(acc2[0]) : "l"(__double_as_longlong(q0.x)), "l"(kv2));
            asm("fma.rn.f32x2 %0, %1, %2, %0;" : "+l"(acc2[1]) : "l"(__double_as_longlong(q0.y)), "l"(kv2));
            asm("fma.rn.f32x2 %0, %1, %2, %0;" : "+l"(acc2[2]) : "l"(__double_as_longlong(q1.x)), "l"(kv2));
            asm("fma.rn.f32x2 %0, %1, %2, %0;" : "+l"(acc2[3]) : "l"(__double_as_longlong(q1.y)), "l"(kv2));
            asm("fma.rn.f32x2 %0, %1, %2, %0;" : "+l"(acc2[4]) : "l"(__double_as_longlong(q2.x)), "l"(kv2));
            asm("fma.rn.f32x2 %0, %1, %2, %0;" : "+l"(acc2[5]) : "l"(__double_as_longlong(q2.y)), "l"(kv2));
            asm("fma.rn.f32x2 %0, %1, %2, %0;" : "+l"(acc2[6]) : "l"(__double_as_longlong(q3.x)), "l"(kv2));
            asm("fma.rn.f32x2 %0, %1, %2, %0;" : "+l"(acc2[7]) : "l"(__double_as_longlong(q3.y)), "l"(kv2));
        }
        #pragma unroll
        for (int j = 0; j < KB; ++j) kva[j] = kvb[j];
    }

    float accf[TM];
    #pragma unroll
    for (int m = 0; m < TM/2; ++m){
        float lo, hi;
        asm("mov.b64 {%0,%1}, %2;" : "=f"(lo), "=f"(hi) : "l"(acc2[m]));
        accf[2*m]     = lo;
        accf[2*m + 1] = hi;
    }

    __syncthreads();               // As no longer needed; reuse for half-combine
    float* redm = As;              // 16*128 floats = 8 KB
    if (half == 1){
        #pragma unroll
        for (int m = 0; m < TM; ++m) redm[m*DD + d] = accf[m];
    }
    __syncthreads();
    if (half == 0){
        #pragma unroll
        for (int m = 0; m < TM; ++m){
            atomicAdd(&out[(size_t)(m0 + m)*DD + d], accf[m] + redm[m*DD + d]);
        }
    }
}

// ---------------- launch ----------------
extern "C" void kernel_launch(void* const* d_in, const int* in_sizes, int n_in,
                              void* d_out, int out_size){
    (void)in_sizes; (void)n_in; (void)out_size;
    const int*   concepts = (const int*)  d_in[0];
    const int*   clen     = (const int*)  d_in[1];
    const int*   segl     = (const int*)  d_in[2];
    const float* embedw   = (const float*)d_in[3];
    const float* kb       = (const float*)d_in[4];
    const float* edge     = (const float*)d_in[5];
    const float* aff      = (const float*)d_in[6];
    const float* lam      = (const float*)d_in[7];
    float* out = (float*)d_out;

    ctx_kernel <<<BB, 1024>>>(concepts, clen, segl, embedw);
    cos_kernel <<<VV/8, 256>>>(kb, out);
    attn_kernel<<<BB*SS, NT_ATTN>>>(concepts, clen, segl, edge, aff, lam);
    gemm_kernel<<<dim3(16, KSPLIT), 256>>>(kb, segl, out);
}

// round 6
// speedup vs baseline: 1.7478x; 1.1825x over previous
#include <cuda_runtime.h>

#define BB 8
#define SS 32
#define PP 8
#define VV 8000
#define DD 128
#define CONCF 5.0f
#define EPSF 1e-8f

#define NT_ATTN 512
#define NQ (VV/4)        /* 2000 float4 per row */

/* ---- gemm config ---- */
#define GTM 32           /* m per CTA = full b */
#define GKSPLIT 50
#define GVT 160          /* v per CTA */
#define GKC 16           /* v sub-chunk */
#define GNCH (GVT/GKC)   /* 10 */
#define ASTR 36          /* padded As row stride (floats), 16B-aligned */

// ---------------- scratch (device globals, no allocations) ----------------
__device__ float g_cn[BB*DD];
__device__ float g_cos[BB*VV];
__device__ float g_Abar[(size_t)BB*SS*VV];    // [B*S, V] (8 MB)

__device__ __forceinline__ float warpReduceSum(float v){
    #pragma unroll
    for (int o = 16; o > 0; o >>= 1) v += __shfl_down_sync(0xffffffffu, v, o);
    return v;
}
__device__ __forceinline__ unsigned long long splat2(float f){
    unsigned long long r; asm("mov.b64 %0, {%1,%1};" : "=l"(r) : "f"(f)); return r;
}
__device__ __forceinline__ void fma2(unsigned long long& a, unsigned long long x, unsigned long long y){
    asm("fma.rn.f32x2 %0, %1, %2, %0;" : "+l"(a) : "l"(x), "l"(y));
}

// ---------------- kernel 1: context + normalize (parallel over s) ----------------
__global__ void __launch_bounds__(1024)
ctx_kernel(const int* __restrict__ concepts,
           const int* __restrict__ clen,
           const int* __restrict__ segl,
           const float* __restrict__ embedw){
    __shared__ float sm[8*DD];
    __shared__ float redn[32];
    int b = blockIdx.x;
    int g = threadIdx.x >> 7;
    int d = threadIdx.x & 127;
    int seg = segl[b];

    float part = 0.f;
    for (int s = g; s < seg; s += 8){
        int bs = b*SS + s;
        int len = clen[bs];
        if (len > 0){
            const int4* ci = (const int4*)(concepts + bs*PP);
            int4 c0 = ci[0], c1 = ci[1];
            float sum = 0.f;
            if (0 < len) sum += __ldg(&embedw[(size_t)c0.x*DD + d]);
            if (1 < len) sum += __ldg(&embedw[(size_t)c0.y*DD + d]);
            if (2 < len) sum += __ldg(&embedw[(size_t)c0.z*DD + d]);
            if (3 < len) sum += __ldg(&embedw[(size_t)c0.w*DD + d]);
            if (4 < len) sum += __ldg(&embedw[(size_t)c1.x*DD + d]);
            if (5 < len) sum += __ldg(&embedw[(size_t)c1.y*DD + d]);
            if (6 < len) sum += __ldg(&embedw[(size_t)c1.z*DD + d]);
            if (7 < len) sum += __ldg(&embedw[(size_t)c1.w*DD + d]);
            part += sum / (float)len;
        }
    }
    sm[g*DD + d] = part;
    __syncthreads();

    float ctx = 0.f;
    #pragma unroll
    for (int k = 0; k < 8; ++k) ctx += sm[k*DD + d];
    ctx /= (float)seg;

    int warp = threadIdx.x >> 5, lane = threadIdx.x & 31;
    float sq = warpReduceSum(ctx*ctx);
    if (lane == 0) redn[warp] = sq;
    __syncthreads();
    float n2 = redn[0] + redn[1] + redn[2] + redn[3];
    if (g == 0) g_cn[b*DD + d] = ctx / fmaxf(sqrtf(n2), EPSF);
}

// ---------------- kernel 2: abs cosine sim + fused output zeroing ----------------
__global__ void cos_kernel(const float* __restrict__ kb, float* __restrict__ out){
    if (blockIdx.x < (BB*SS*DD)/256)
        out[blockIdx.x*256 + threadIdx.x] = 0.f;

    int warp = threadIdx.x >> 5, lane = threadIdx.x & 31;
    int v = blockIdx.x*8 + warp;
    if (v >= VV) return;
    const float4* row4 = (const float4*)(kb + (size_t)v*DD);
    float4 kv = row4[lane];
    float nr = kv.x*kv.x + kv.y*kv.y + kv.z*kv.z + kv.w*kv.w;
    nr = warpReduceSum(nr);
    nr = __shfl_sync(0xffffffffu, nr, 0);
    float inv = 1.0f / fmaxf(sqrtf(nr), EPSF);
    #pragma unroll
    for (int b = 0; b < BB; ++b){
        const float4* cn4 = (const float4*)(g_cn + b*DD);
        float4 c = cn4[lane];
        float dt = kv.x*c.x + kv.y*c.y + kv.z*c.z + kv.w*c.w;
        dt = warpReduceSum(dt);
        if (lane == 0) g_cos[(size_t)b*VV + v] = fabsf(dt)*inv;
    }
}

// ---------------- kernel 3: register-resident fused attention ----------------
__global__ void __launch_bounds__(NT_ATTN, 1)
attn_kernel(const int* __restrict__ concepts,
            const int* __restrict__ clen,
            const int* __restrict__ segl,
            const float* __restrict__ edge,
            const float* __restrict__ aff,
            const float* __restrict__ lam){
    __shared__ float red[32];
    int bs = blockIdx.x;
    int b = bs >> 5, s = bs & 31;
    int tid = threadIdx.x;
    int warp = tid >> 5, lane = tid & 31;

    float4 racc[4];
    #pragma unroll
    for (int k = 0; k < 4; ++k) racc[k] = make_float4(0.f, 0.f, 0.f, 0.f);

    int seg = segl[b];
    int len = (s < seg) ? clen[bs] : 0;

    if (len > 0){
        float invden = 1.0f / (float)len;
        const float4* cos4 = (const float4*)(g_cos + (size_t)b*VV);
        const float4* lam4 = (const float4*)lam;
        const float4* aff4 = (const float4*)aff;
        const int*    cp   = concepts + bs*PP;

        float4 A[4], Bv[4];
        #pragma unroll
        for (int k = 0; k < 4; ++k){
            int i = tid + k*NT_ATTN;
            if (i < NQ){
                float4 l  = lam4[i];
                float4 cf = cos4[i];
                float4 af = aff4[i];
                A[k].x = CONCF*l.x*cf.x; A[k].y = CONCF*l.y*cf.y;
                A[k].z = CONCF*l.z*cf.z; A[k].w = CONCF*l.w*cf.w;
                Bv[k].x = CONCF*(1.f-l.x)*af.x; Bv[k].y = CONCF*(1.f-l.y)*af.y;
                Bv[k].z = CONCF*(1.f-l.z)*af.z; Bv[k].w = CONCF*(1.f-l.w)*af.w;
            }
        }

        float4 E[4], F[4];
        {
            int c = __ldg(&cp[0]);
            const float4* r = (const float4*)(edge + (size_t)c*VV);
            #pragma unroll
            for (int k = 0; k < 4; ++k){
                int i = tid + k*NT_ATTN;
                if (i < NQ) E[k] = __ldcs(&r[i]);
            }
        }

        for (int p = 0; p < len; ++p){
            if (p + 1 < len){
                int c = __ldg(&cp[p+1]);
                const float4* r = (const float4*)(edge + (size_t)c*VV);
                #pragma unroll
                for (int k = 0; k < 4; ++k){
                    int i = tid + k*NT_ATTN;
                    if (i < NQ) F[k] = __ldcs(&r[i]);
                }
            }

            float mx = -1e30f, mn = 1e30f;
            #pragma unroll
            for (int k = 0; k < 4; ++k){
                int i = tid + k*NT_ATTN;
                if (i < NQ){
                    mx = fmaxf(mx, fmaxf(fmaxf(E[k].x, E[k].y), fmaxf(E[k].z, E[k].w)));
                    mn = fminf(mn, fminf(fminf(E[k].x, E[k].y), fminf(E[k].z, E[k].w)));
                }
            }
            #pragma unroll
            for (int o = 16; o > 0; o >>= 1){
                mx = fmaxf(mx, __shfl_down_sync(0xffffffffu, mx, o));
                mn = fminf(mn, __shfl_down_sync(0xffffffffu, mn, o));
            }
            __syncthreads();
            if (lane == 0){ red[warp] = mx; red[16 + warp] = mn; }
            __syncthreads();
            float rmx = -1e30f, rmn = 1e30f;
            #pragma unroll
            for (int i = 0; i < 16; ++i){
                rmx = fmaxf(rmx, red[i]);
                rmn = fminf(rmn, red[16 + i]);
            }
            float rng  = rmx - rmn;
            float invr = 1.0f / (rng + ((rng == 0.0f) ? 1.0f : 0.0f));

            float ss = 0.f;
            #pragma unroll
            for (int k = 0; k < 4; ++k){
                int i = tid + k*NT_ATTN;
                if (i < NQ){
                    float4 ex;
                    ex.x = __expf((E[k].x*invr)*A[k].x + ((E[k].x > 0.f) ? Bv[k].x : 0.f));
                    ex.y = __expf((E[k].y*invr)*A[k].y + ((E[k].y > 0.f) ? Bv[k].y : 0.f));
                    ex.z = __expf((E[k].z*invr)*A[k].z + ((E[k].z > 0.f) ? Bv[k].z : 0.f));
                    ex.w = __expf((E[k].w*invr)*A[k].w + ((E[k].w > 0.f) ? Bv[k].w : 0.f));
                    E[k] = ex;
                    ss += (ex.x + ex.y) + (ex.z + ex.w);
                }
            }
            ss = warpReduceSum(ss);
            __syncthreads();
            if (lane == 0) red[warp] = ss;
            __syncthreads();
            float tot = 0.f;
            #pragma unroll
            for (int i = 0; i < 16; ++i) tot += red[i];
            float scale = invden / tot;

            #pragma unroll
            for (int k = 0; k < 4; ++k){
                int i = tid + k*NT_ATTN;
                if (i < NQ){
                    racc[k].x += E[k].x*scale;
                    racc[k].y += E[k].y*scale;
                    racc[k].z += E[k].z*scale;
                    racc[k].w += E[k].w*scale;
                }
            }
            #pragma unroll
            for (int k = 0; k < 4; ++k) E[k] = F[k];
        }
    }

    float4* ob = (float4*)(g_Abar + (size_t)bs*VV);
    #pragma unroll
    for (int k = 0; k < 4; ++k){
        int i = tid + k*NT_ATTN;
        if (i < NQ) ob[i] = racc[k];
    }
}

// ---------------- kernel 4: register-tiled GEMM out[256,128] = Abar @ kb ----------------
// warp = 4-m group (m-tile 32 = one batch b), lane = 4-d group.
// Thread tile 4m x 4d; FFMA2 pairs over m (packed double2 from As), d splatted.
__global__ void __launch_bounds__(256)
gemm_kernel(const float* __restrict__ kb,
            const int* __restrict__ segl,
            float* __restrict__ out){
    __shared__ __align__(16) float As[2][GKC*ASTR];   // [v][m] padded, 2.3 KB x2
    __shared__ __align__(16) float Bs[2][GKC*DD];     // [v][d], 8 KB x2
    int mt = blockIdx.x;             // == b
    int ks = blockIdx.y;
    int m0 = mt*GTM;
    int seg = segl[mt];
    int tid = threadIdx.x;
    int mg  = tid >> 5;              // warp id -> m group
    int dg  = tid & 31;              // lane    -> d group
    int v0  = ks*GVT;
    bool active = (mg*4 < seg);      // whole-warp skip for masked s rows

    // loader roles
    int am  = tid >> 2, avq = tid & 3;                 // As: threads 0..127
    const float* aptr = &g_Abar[(size_t)(m0 + am)*VV + v0];
    int bdq = tid & 31;                                // Bs: all 256, 2 float4 each
    int bv0 = tid >> 5, bv1 = (tid + 256) >> 5;
    const float* bptr = &kb[(size_t)v0*DD];

    float4 rA, rB0, rB1;
    // ldg chunk 0
    if (tid < 128) rA = *(const float4*)(aptr + avq*4);
    rB0 = *(const float4*)(bptr + (size_t)bv0*DD + bdq*4);
    rB1 = *(const float4*)(bptr + (size_t)bv1*DD + bdq*4);
    // sts chunk 0
    if (tid < 128){
        As[0][(avq*4 + 0)*ASTR + am] = rA.x;
        As[0][(avq*4 + 1)*ASTR + am] = rA.y;
        As[0][(avq*4 + 2)*ASTR + am] = rA.z;
        As[0][(avq*4 + 3)*ASTR + am] = rA.w;
    }
    *(float4*)(&Bs[0][bv0*DD + bdq*4]) = rB0;
    *(float4*)(&Bs[0][bv1*DD + bdq*4]) = rB1;
    __syncthreads();

    unsigned long long acc[8];
    #pragma unroll
    for (int i = 0; i < 8; ++i) acc[i] = 0ULL;

    for (int c = 0; c < GNCH; ++c){
        if (c + 1 < GNCH){
            int vc = (c + 1)*GKC;
            if (tid < 128) rA = *(const float4*)(aptr + vc + avq*4);
            rB0 = *(const float4*)(bptr + (size_t)(vc + bv0)*DD + bdq*4);
            rB1 = *(const float4*)(bptr + (size_t)(vc + bv1)*DD + bdq*4);
        }
        if (active){
            const float* AsB = As[c & 1];
            const float* BsB = Bs[c & 1];
            #pragma unroll
            for (int v = 0; v < GKC; ++v){
                double2 av = *(const double2*)(AsB + v*ASTR + mg*4);   // (a0,a1),(a2,a3) broadcast
                float4  bv = *(const float4*) (BsB + v*DD  + dg*4);
                unsigned long long a01 = __double_as_longlong(av.x);
                unsigned long long a23 = __double_as_longlong(av.y);
                unsigned long long b0 = splat2(bv.x);
                unsigned long long b1 = splat2(bv.y);
                unsigned long long b2 = splat2(bv.z);
                unsigned long long b3 = splat2(bv.w);
                fma2(acc[0], a01, b0); fma2(acc[1], a01, b1);
                fma2(acc[2], a01, b2); fma2(acc[3], a01, b3);
                fma2(acc[4], a23, b0); fma2(acc[5], a23, b1);
                fma2(acc[6], a23, b2); fma2(acc[7], a23, b3);
            }
        }
        if (c + 1 < GNCH){
            int bb = (c + 1) & 1;
            if (tid < 128){
                As[bb][(avq*4 + 0)*ASTR + am] = rA.x;
                As[bb][(avq*4 + 1)*ASTR + am] = rA.y;
                As[bb][(avq*4 + 2)*ASTR + am] = rA.z;
                As[bb][(avq*4 + 3)*ASTR + am] = rA.w;
            }
            *(float4*)(&Bs[bb][bv0*DD + bdq*4]) = rB0;
            *(float4*)(&Bs[bb][bv1*DD + bdq*4]) = rB1;
        }
        __syncthreads();
    }

    if (active){
        int mbase = m0 + mg*4;
        int dbase = dg*4;
        #pragma unroll
        for (int mp = 0; mp < 2; ++mp){
            #pragma unroll
            for (int dj = 0; dj < 4; ++dj){
                float lo, hi;
                asm("mov.b64 {%0,%1}, %2;" : "=f"(lo), "=f"(hi) : "l"(acc[mp*4 + dj]));
                atomicAdd(&out[(size_t)(mbase + 2*mp    )*DD + dbase + dj], lo);
                atomicAdd(&out[(size_t)(mbase + 2*mp + 1)*DD + dbase + dj], hi);
            }
        }
    }
}

// ---------------- launch ----------------
extern "C" void kernel_launch(void* const* d_in, const int* in_sizes, int n_in,
                              void* d_out, int out_size){
    (void)in_sizes; (void)n_in; (void)out_size;
    const int*   concepts = (const int*)  d_in[0];
    const int*   clen     = (const int*)  d_in[1];
    const int*   segl     = (const int*)  d_in[2];
    const float* embedw   = (const float*)d_in[3];
    const float* kb       = (const float*)d_in[4];
    const float* edge     = (const float*)d_in[5];
    const float* aff      = (const float*)d_in[6];
    const float* lam      = (const float*)d_in[7];
    float* out = (float*)d_out;

    ctx_kernel <<<BB, 1024>>>(concepts, clen, segl, embedw);
    cos_kernel <<<VV/8, 256>>>(kb, out);
    attn_kernel<<<BB*SS, NT_ATTN>>>(concepts, clen, segl, edge, aff, lam);
    gemm_kernel<<<dim3(BB, GKSPLIT), 256>>>(kb, segl, out);
}